// round 10
// baseline (speedup 1.0000x reference)
#include <cuda_runtime.h>
#include <cuda_fp16.h>
#include <cstdint>

// Problem dims
constexpr int B_    = 8;
constexpr int H_    = 9;
constexpr int E_    = 128;
constexpr int S_    = 1025;
constexpr int HE_   = H_ * E_;      // 1152
constexpr int SPAD_ = 1032;         // padded S (halfs), 16B-multiple rows
constexpr int K3_   = 3 * E_;       // 384: split folded into K
constexpr long long QK3 = (long long)B_ * H_ * S_ * K3_;

// Scratch (device globals) — all fp16
__device__ __half g_x [(long long)B_ * S_ * K3_];      // [b][s][ xh | xh | xl ]
__device__ __half g_pt[3 * H_ * E_ * K3_];             // [p*H+h][f][ Ph | Pl | Ph ]
__device__ __half g_wh[E_ * HE_];                      // W [e][k] fp16
__device__ __half g_q [QK3];                           // [bh][s][ qh | qh | ql ]
__device__ __half g_k [QK3];                           // [bh][s][ kh | kl | kh ]
__device__ __half g_v [(long long)B_ * H_ * E_ * SPAD_];   // v^T [bh][f][t]
__device__ __half g_ah[(long long)B_ * H_ * S_ * SPAD_];   // atten fp16 [bh][s][t]
__device__ __half g_o [(long long)B_ * S_ * HE_];      // [b][s][h*E+f]

// ---------------------------------------------------------------------------
// async-copy / mma helpers
// ---------------------------------------------------------------------------
__device__ __forceinline__ void cp_async16h(uint32_t dst, const __half* src, bool p) {
    int sz = p ? 16 : 0;   // src-size 0 => 16-byte zero-fill at dst
    asm volatile("cp.async.cg.shared.global [%0], [%1], 16, %2;\n"
                 :: "r"(dst), "l"(src), "r"(sz));
}
__device__ __forceinline__ void cp_commit() {
    asm volatile("cp.async.commit_group;\n" ::: "memory");
}
template <int N>
__device__ __forceinline__ void cp_wait() {
    asm volatile("cp.async.wait_group %0;\n" :: "n"(N) : "memory");
}
__device__ __forceinline__ void ldsm4(uint32_t addr, uint32_t r[4]) {
    asm volatile("ldmatrix.sync.aligned.m8n8.x4.shared.b16 {%0,%1,%2,%3}, [%4];"
                 : "=r"(r[0]), "=r"(r[1]), "=r"(r[2]), "=r"(r[3]) : "r"(addr));
}
__device__ __forceinline__ void mma16h(float* c, const uint32_t a[4],
                                       uint32_t b0, uint32_t b1)
{
    asm volatile(
        "mma.sync.aligned.m16n8k16.row.col.f32.f16.f16.f32 "
        "{%0,%1,%2,%3},{%4,%5,%6,%7},{%8,%9},{%0,%1,%2,%3};"
        : "+f"(c[0]), "+f"(c[1]), "+f"(c[2]), "+f"(c[3])
        : "r"(a[0]), "r"(a[1]), "r"(a[2]), "r"(a[3]), "r"(b0), "r"(b1));
}

// ---------------------------------------------------------------------------
// Uniform fp16 GEMM core (split precision folded into K by operand concat).
// Operands K-contiguous halfs: X[outer][k], row stride ld (halfs).
// smem tiles [outer 128][k 32], row stride LDH=40 halfs (80B rows:
// ldmatrix rows on 8 distinct bank groups; 16B aligned).
// 256 thr = 8 warps (4m x 2n), warp 32x64, m16n8k16 via ldmatrix.x4.b16.
// 4-stage cp.async ring, 3 tiles in flight, ONE __syncthreads per ktile.
// EPI: 0 = fp32 C=acc*scale(+bias); 1 = fp16 hi->C[gn], hi->C[gn+o2],
//      lo->C[gn+ol] (K-concat producer); 2 = fp16 C.
// ---------------------------------------------------------------------------
constexpr int LDH    = 40;              // halfs per smem row
constexpr int TILE_B = 128 * LDH * 2;   // 10240 B per operand tile
constexpr int STG_B  = 2 * TILE_B;      // 20480 B per stage (A+B)
constexpr int SMEM_BYTES = 4 * STG_B;   // 81920 B, 2 CTAs/SM

template<int EPI>
__device__ __forceinline__ void hgemm(
    const __half* __restrict__ A, long long lda, int kalim,
    const __half* __restrict__ Bp, long long ldb, int kblim,
    void* __restrict__ Cv, long long c_m, long long c_n,
    int M, int N, int K, float scale, const float* __restrict__ bias,
    int o2, int ol)
{
    extern __shared__ __half smh[];

    const int tid  = threadIdx.x;
    const int lane = tid & 31;
    const int wid  = tid >> 5;
    const int g    = lane >> 2;
    const int tg   = lane & 3;
    const int wm   = (wid & 3) * 32;
    const int wn   = (wid >> 2) * 64;
    const int m0   = blockIdx.x * 128;
    const int n0   = blockIdx.y * 128;

    const uint32_t smb = (uint32_t)__cvta_generic_to_shared(smh);

    auto load_op = [&](const __half* src, long long ld, int klim, int o0,
                       int onum, int k0, uint32_t dst) {
#pragma unroll
        for (int it = 0; it < 2; ++it) {
            int idx = it * 256 + tid;       // 512 chunks of 8 halfs
            int o  = idx >> 2;
            int kh = (idx & 3) * 8;
            int go = o0 + o, gk = k0 + kh;
            bool p = (go < onum) && (gk + 8 <= klim);
            const __half* s = p ? (src + (long long)go * ld + gk) : src;
            cp_async16h(dst + (uint32_t)((o * LDH + kh) * 2), s, p);
        }
    };
    auto load_tile = [&](int kt, int stage) {
        const int k0 = kt * 32;
        const uint32_t sb = smb + (uint32_t)(stage * STG_B);
        load_op(A,  lda, kalim, m0, M, k0, sb);
        load_op(Bp, ldb, kblim, n0, N, k0, sb + TILE_B);
    };

    float acc[2][8][4];
#pragma unroll
    for (int i = 0; i < 2; ++i)
#pragma unroll
        for (int j = 0; j < 8; ++j)
#pragma unroll
            for (int r = 0; r < 4; ++r) acc[i][j][r] = 0.0f;

    const int ktiles = (K + 31) / 32;

    // prologue: 3 tiles in flight (one commit group each; empty groups ok)
#pragma unroll
    for (int i = 0; i < 3; ++i) {
        if (i < ktiles) load_tile(i, i);
        cp_commit();
    }

    // ldmatrix per-lane byte offsets within an operand tile
    const uint32_t aoff = (uint32_t)(
        (wm + (lane & 7) + 8 * ((lane >> 3) & 1)) * LDH * 2 + 16 * (lane >> 4));
    const uint32_t boff = (uint32_t)(
        (wn + (lane & 7) + 8 * ((lane >> 4) & 1)) * LDH * 2 + 16 * ((lane >> 3) & 1));

    for (int kt = 0; kt < ktiles; ++kt) {
        cp_wait<2>();              // tile kt complete (3 in flight max)
        __syncthreads();           // visibility + stage-reuse safety

        int nt = kt + 3;
        if (nt < ktiles) load_tile(nt, nt & 3);
        cp_commit();

        const uint32_t sb = smb + (uint32_t)((kt & 3) * STG_B);
        const uint32_t aH = sb + aoff;
        const uint32_t bH = sb + TILE_B + boff;

#pragma unroll
        for (int ks = 0; ks < 2; ++ks) {            // two k16 steps
            const uint32_t ko = ks * 32;            // 16 halfs
            uint32_t AH[2][4];
#pragma unroll
            for (int mf = 0; mf < 2; ++mf)
                ldsm4(aH + mf * (16 * LDH * 2) + ko, AH[mf]);
#pragma unroll
            for (int p = 0; p < 4; ++p) {
                uint32_t BH[4];
                ldsm4(bH + p * (16 * LDH * 2) + ko, BH);
#pragma unroll
                for (int mf = 0; mf < 2; ++mf) {
                    mma16h(acc[mf][2 * p],     AH[mf], BH[0], BH[1]);
                    mma16h(acc[mf][2 * p + 1], AH[mf], BH[2], BH[3]);
                }
            }
        }
    }

    // ---- epilogue ----
#pragma unroll
    for (int mf = 0; mf < 2; ++mf) {
#pragma unroll
        for (int nf = 0; nf < 8; ++nf) {
            const int r0 = m0 + wm + mf * 16 + g;
            const int cb = n0 + wn + nf * 8 + 2 * tg;
#pragma unroll
            for (int h = 0; h < 2; ++h) {
                int gm = h ? (r0 + 8) : r0;
                if (gm >= M) continue;
#pragma unroll
                for (int q = 0; q < 2; ++q) {
                    int gn = cb + q;
                    if (gn >= N) continue;
                    float v = acc[mf][nf][h * 2 + q];
                    long long off = (long long)gm * c_m + (long long)gn * c_n;
                    if (EPI == 0) {
                        v *= scale;
                        if (bias) v += bias[gn];
                        ((float*)Cv)[off] = v;
                    } else if (EPI == 1) {
                        __half* C = (__half*)Cv;
                        __half hi = __float2half_rn(v);
                        C[off]      = hi;
                        C[off + o2] = hi;
                        C[off + ol] = __float2half_rn(v - __half2float(hi));
                    } else {
                        ((__half*)Cv)[off] = __float2half_rn(v);
                    }
                }
            }
        }
    }
}

// ---------------------------------------------------------------------------
// Prep 1: x [b][E][S] -> g_x [b][s][ xh | xh | xl ]
// ---------------------------------------------------------------------------
__global__ void prep_x_kernel(const float* __restrict__ x)
{
    __shared__ float t[32][33];
    const int b  = blockIdx.z;
    const int s0 = blockIdx.x * 32;
    const int e0 = blockIdx.y * 32;
    const int tx = threadIdx.x, ty = threadIdx.y;
#pragma unroll
    for (int j = 0; j < 4; ++j) {
        int e = e0 + ty + j * 8, s = s0 + tx;
        if (e < E_ && s < S_) t[ty + j * 8][tx] = x[((long long)b * E_ + e) * S_ + s];
    }
    __syncthreads();
#pragma unroll
    for (int j = 0; j < 4; ++j) {
        int s = s0 + ty + j * 8, e = e0 + tx;
        if (s < S_ && e < E_) {
            float v = t[tx][ty + j * 8];
            __half hi = __float2half_rn(v);
            __half lo = __float2half_rn(v - __half2float(hi));
            long long o = ((long long)b * S_ + s) * K3_ + e;
            g_x[o]            = hi;
            g_x[o + E_]       = hi;
            g_x[o + 2 * E_]   = lo;
        }
    }
}

// ---------------------------------------------------------------------------
// Prep 2: {Q,K,V} [h][e][f] -> g_pt [p*H+h][f][ Ph | Pl | Ph ]
// ---------------------------------------------------------------------------
__global__ void prep_qkv_kernel(const float* __restrict__ Qm,
                                const float* __restrict__ Km,
                                const float* __restrict__ Vm)
{
    __shared__ float t[32][33];
    const int z = blockIdx.z;          // p*H + h
    const int p = z / H_, h = z % H_;
    const float* src = (p == 0 ? Qm : (p == 1 ? Km : Vm)) + (long long)h * E_ * E_;
    const int f0 = blockIdx.x * 32;
    const int e0 = blockIdx.y * 32;
    const int tx = threadIdx.x, ty = threadIdx.y;
#pragma unroll
    for (int j = 0; j < 4; ++j) {
        int e = e0 + ty + j * 8, f = f0 + tx;
        t[ty + j * 8][tx] = src[e * E_ + f];
    }
    __syncthreads();
#pragma unroll
    for (int j = 0; j < 4; ++j) {
        int f = f0 + ty + j * 8, e = e0 + tx;
        float v = t[tx][ty + j * 8];
        __half hi = __float2half_rn(v);
        __half lo = __float2half_rn(v - __half2float(hi));
        long long o = ((long long)z * E_ + f) * K3_ + e;
        g_pt[o]          = hi;
        g_pt[o + E_]     = lo;
        g_pt[o + 2*E_]   = hi;
    }
}

// ---------------------------------------------------------------------------
// Prep 3: W -> fp16; zero g_v pad columns
// ---------------------------------------------------------------------------
__global__ void prep_w_kernel(const float* __restrict__ W)
{
    int i = blockIdx.x * 256 + threadIdx.x;
    if (i < E_ * HE_) g_wh[i] = __float2half_rn(W[i]);
    if (i < B_ * H_ * E_ * (SPAD_ - S_)) {
        int j  = i % (SPAD_ - S_);
        int bf = i / (SPAD_ - S_);
        g_v[(long long)bf * SPAD_ + S_ + j] = __float2half_rn(0.0f);
    }
}

// ---------------------------------------------------------------------------
// Stage 1: qkv. A=g_x [s][384], B=g_pt [f][384]. K=384 folds the split.
//   p=0 -> g_q [ qh | qh | ql ];  p=1 -> g_k [ kh | kl | kh ];  p=2 -> g_v.
// ---------------------------------------------------------------------------
__global__ __launch_bounds__(256, 2) void qkv_kernel()
{
    const int z  = blockIdx.z;
    const int p  = z / (B_ * H_);
    const int bh = z % (B_ * H_);
    const int b  = bh / H_;
    const int h  = bh % H_;
    const __half* A  = g_x  + (long long)b * S_ * K3_;
    const __half* Bp = g_pt + (long long)(p * H_ + h) * E_ * K3_;
    if (p == 0) {
        hgemm<1>(A, K3_, K3_, Bp, K3_, K3_,
                 g_q + (long long)bh * S_ * K3_, K3_, 1,
                 S_, E_, K3_, 1.0f, nullptr, E_, 2 * E_);
    } else if (p == 1) {
        hgemm<1>(A, K3_, K3_, Bp, K3_, K3_,
                 g_k + (long long)bh * S_ * K3_, K3_, 1,
                 S_, E_, K3_, 1.0f, nullptr, 2 * E_, E_);
    } else {
        hgemm<2>(A, K3_, K3_, Bp, K3_, K3_,
                 g_v + (long long)bh * E_ * SPAD_, 1, SPAD_,
                 S_, E_, K3_, 1.0f, nullptr, 0, 0);
    }
}

// ---------------------------------------------------------------------------
// Stage 2: scores. A=g_q, B=g_k, K=384 -> exactly qh*kh + qh*kl + ql*kh.
// ---------------------------------------------------------------------------
__global__ __launch_bounds__(256, 2) void scores_kernel(float* __restrict__ att)
{
    const int bh = blockIdx.z;
    const long long qo = (long long)bh * S_ * K3_;
    hgemm<0>(g_q + qo, K3_, K3_, g_k + qo, K3_, K3_,
             att + (long long)bh * S_ * S_, S_, 1,
             S_, S_, K3_, 0.08838834764831845f, nullptr, 0, 0);
}

// ---------------------------------------------------------------------------
// Stage 3: softmax in-place (fp32) + padded fp16 copy for av.
// ---------------------------------------------------------------------------
__global__ __launch_bounds__(256) void softmax_kernel(float* __restrict__ att)
{
    const long long row = blockIdx.x;
    float* p = att + row * (long long)S_;
    __half* ph = g_ah + row * (long long)SPAD_;
    const int tid = threadIdx.x;

    float v[5];
    float mx = -3.4e38f;
#pragma unroll
    for (int i = 0; i < 5; ++i) {
        int idx = tid + i * 256;
        v[i] = (idx < S_) ? p[idx] : -3.4e38f;
        mx = fmaxf(mx, v[i]);
    }
    __shared__ float redm[8];
    __shared__ float reds[8];
#pragma unroll
    for (int o = 16; o > 0; o >>= 1) mx = fmaxf(mx, __shfl_xor_sync(0xffffffffu, mx, o));
    if ((tid & 31) == 0) redm[tid >> 5] = mx;
    __syncthreads();
    mx = redm[0];
#pragma unroll
    for (int w = 1; w < 8; ++w) mx = fmaxf(mx, redm[w]);

    float sum = 0.0f;
#pragma unroll
    for (int i = 0; i < 5; ++i) {
        int idx = tid + i * 256;
        if (idx < S_) { v[i] = __expf(v[i] - mx); sum += v[i]; }
        else v[i] = 0.0f;
    }
#pragma unroll
    for (int o = 16; o > 0; o >>= 1) sum += __shfl_xor_sync(0xffffffffu, sum, o);
    if ((tid & 31) == 0) reds[tid >> 5] = sum;
    __syncthreads();
    sum = reds[0];
#pragma unroll
    for (int w = 1; w < 8; ++w) sum += reds[w];
    const float inv = __frcp_rn(sum);

#pragma unroll
    for (int i = 0; i < 5; ++i) {
        int idx = tid + i * 256;
        if (idx < S_) {
            float a = v[i] * inv;
            p[idx]  = a;
            ph[idx] = __float2half_rn(a);
        }
    }
    if (tid < SPAD_ - S_) ph[S_ + tid] = __float2half_rn(0.0f);
}

// ---------------------------------------------------------------------------
// Stage 4: av (single fp16). A=g_ah [s][t], B=g_v [f][t], K=S.
// ---------------------------------------------------------------------------
__global__ __launch_bounds__(256, 2) void av_kernel()
{
    const int bh = blockIdx.z;
    const int b = bh / H_;
    const int h = bh % H_;
    hgemm<2>(g_ah + (long long)bh * S_ * SPAD_, SPAD_, SPAD_,
             g_v  + (long long)bh * E_ * SPAD_, SPAD_, SPAD_,
             g_o + (long long)b * S_ * HE_ + (long long)h * E_, HE_, 1,
             S_, E_, S_, 1.0f, nullptr, 0, 0);
}

// ---------------------------------------------------------------------------
// Stage 5: proj (single fp16). A=g_o [s][k], B=g_wh [e][k], K=1152.
// ---------------------------------------------------------------------------
__global__ __launch_bounds__(256, 2) void proj_kernel(
    const float* __restrict__ bias, float* __restrict__ out)
{
    const int b = blockIdx.z;
    hgemm<0>(g_o + (long long)b * S_ * HE_, HE_, HE_,
             g_wh, HE_, HE_,
             out + (long long)b * E_ * S_, 1, S_,
             S_, E_, HE_, 1.0f, bias, 0, 0);
}

// ---------------------------------------------------------------------------
extern "C" void kernel_launch(void* const* d_in, const int* in_sizes, int n_in,
                              void* d_out, int out_size)
{
    (void)in_sizes; (void)n_in; (void)out_size;
    const float* x    = (const float*)d_in[0];
    const float* Qm   = (const float*)d_in[1];
    const float* Km   = (const float*)d_in[2];
    const float* Vm   = (const float*)d_in[3];
    const float* W    = (const float*)d_in[4];
    const float* bias = (const float*)d_in[5];

    float* out = (float*)d_out;
    float* att = out + (long long)B_ * E_ * S_;   // atten region follows out

    const int MT = (S_ + 127) / 128;  // 9

    static bool attr_done = false;
    if (!attr_done) {
        cudaFuncSetAttribute(qkv_kernel,
            cudaFuncAttributeMaxDynamicSharedMemorySize, SMEM_BYTES);
        cudaFuncSetAttribute(scores_kernel,
            cudaFuncAttributeMaxDynamicSharedMemorySize, SMEM_BYTES);
        cudaFuncSetAttribute(av_kernel,
            cudaFuncAttributeMaxDynamicSharedMemorySize, SMEM_BYTES);
        cudaFuncSetAttribute(proj_kernel,
            cudaFuncAttributeMaxDynamicSharedMemorySize, SMEM_BYTES);
        attr_done = true;
    }

    prep_x_kernel  <<<dim3((S_ + 31) / 32, E_ / 32, B_), dim3(32, 8)>>>(x);
    prep_qkv_kernel<<<dim3(E_ / 32, E_ / 32, 3 * H_),    dim3(32, 8)>>>(Qm, Km, Vm);
    prep_w_kernel  <<<(E_ * HE_ + 255) / 256, 256>>>(W);

    qkv_kernel    <<<dim3(MT, 1, 3 * B_ * H_), 256, SMEM_BYTES>>>();
    scores_kernel <<<dim3(MT, MT, B_ * H_),    256, SMEM_BYTES>>>(att);
    softmax_kernel<<<dim3(B_ * H_ * S_),       256>>>(att);
    av_kernel     <<<dim3(MT, 1, B_ * H_),     256, SMEM_BYTES>>>();
    proj_kernel   <<<dim3(MT, 1, B_),          256, SMEM_BYTES>>>(bias, out);
}